// round 7
// baseline (speedup 1.0000x reference)
#include <cuda_runtime.h>
#include <cstdint>

#define BB 32
#define TT 2048
#define DD 512
#define D4 128
#define ROW_BYTES 2048           // 512 floats
#define RPS 4                    // rows per pipeline stage
#define NSTAGE 4
#define TILE 32                  // contiguous rows per block
#define NTILE (TT / TILE)        // 64
#define NBLK (BB * NTILE)        // 2048 blocks
#define STAGE_BYTES (2 * RPS * ROW_BYTES)   // 16 KB (p half + q half)
#define DSMEM_BYTES (NSTAGE * STAGE_BYTES)  // 64 KB

// Scratch: zero-initialized at module load; finalizing block re-zeros after
// consuming, so every invocation (incl. graph replays) sees zeroed scratch.
__device__ float    g_sumdiff[BB * DD];
__device__ float    g_wl;
__device__ unsigned g_count;   // self-wrapping ticket via atomicInc

__device__ __forceinline__ uint32_t smem_addr(const void* p) {
    return (uint32_t)__cvta_generic_to_shared(p);
}

__device__ __forceinline__ void mbar_init(uint32_t bar, uint32_t count) {
    asm volatile("mbarrier.init.shared.b64 [%0], %1;" :: "r"(bar), "r"(count) : "memory");
}
__device__ __forceinline__ void mbar_expect_tx(uint32_t bar, uint32_t bytes) {
    asm volatile("mbarrier.arrive.expect_tx.shared.b64 _, [%0], %1;"
                 :: "r"(bar), "r"(bytes) : "memory");
}
__device__ __forceinline__ void mbar_wait(uint32_t bar, uint32_t parity) {
    asm volatile(
        "{\n\t"
        ".reg .pred P;\n\t"
        "WAIT_%=:\n\t"
        "mbarrier.try_wait.parity.shared.b64 P, [%0], %1;\n\t"
        "@P bra.uni DONE_%=;\n\t"
        "bra.uni WAIT_%=;\n\t"
        "DONE_%=:\n\t"
        "}"
        :: "r"(bar), "r"(parity) : "memory");
}
__device__ __forceinline__ void bulk_ld(uint32_t dst_smem, const void* src_gmem,
                                        uint32_t bytes, uint32_t bar) {
    asm volatile(
        "cp.async.bulk.shared::cta.global.mbarrier::complete_tx::bytes [%0], [%1], %2, [%3];"
        :: "r"(dst_smem), "l"(src_gmem), "r"(bytes), "r"(bar) : "memory");
}

__device__ __forceinline__ float smooth_l1(float d) {
    float ad = fabsf(d);
    return (ad < 1.0f) ? 0.5f * d * d : ad - 0.5f;
}

__global__ __launch_bounds__(256) void fused_kernel(
    const float* __restrict__ preds,
    const float* __restrict__ targets,
    const int* __restrict__ lens,
    float* __restrict__ out)
{
    extern __shared__ __align__(1024) char dsmem[];
    __shared__ __align__(8) uint64_t bar_mem[NSTAGE];

    const int b    = blockIdx.x >> 6;          // / NTILE
    const int tile = blockIdx.x & (NTILE - 1);
    const int len  = lens[b];
    const int t0   = tile * TILE;
    const int rows = min(TILE, len - t0);      // valid rows in this tile

    const int tid = threadIdx.x;
    const int d4  = tid & 127;                 // float4 lane in D
    const int th  = tid >> 7;                  // row parity within stage

    if (rows > 0) {
        const int nst = (rows + RPS - 1) / RPS;   // stages this block runs

        const char* pg = (const char*)preds   + ((size_t)b * TT + t0) * ROW_BYTES;
        const char* qg = (const char*)targets + ((size_t)b * TT + t0) * ROW_BYTES;

        const uint32_t dsm = smem_addr(dsmem);
        const uint32_t bm  = smem_addr(bar_mem);

        if (tid == 0) {
            for (int s = 0; s < NSTAGE; s++) mbar_init(bm + s * 8, 1);
        }
        __syncthreads();

        // prologue: fill the ring
        if (tid == 0) {
            const int npro = min(nst, NSTAGE);
            for (int s = 0; s < npro; s++) {
                const int nr = min(RPS, rows - s * RPS);
                const uint32_t bytes = (uint32_t)nr * ROW_BYTES;
                const uint32_t bar = bm + (s % NSTAGE) * 8;
                const uint32_t base = dsm + (s % NSTAGE) * STAGE_BYTES;
                mbar_expect_tx(bar, 2 * bytes);
                bulk_ld(base,                   pg + (size_t)s * RPS * ROW_BYTES, bytes, bar);
                bulk_ld(base + RPS * ROW_BYTES, qg + (size_t)s * RPS * ROW_BYTES, bytes, bar);
            }
        }

        float sdx = 0.f, sdy = 0.f, sdz = 0.f, sdw = 0.f;
        float wl = 0.f;

        for (int s = 0; s < nst; s++) {
            const int slot = s % NSTAGE;
            const uint32_t parity = (s / NSTAGE) & 1;
            mbar_wait(bm + slot * 8, parity);

            const int nr = min(RPS, rows - s * RPS);
            const char* base = dsmem + slot * STAGE_BYTES;

            for (int r = th; r < nr; r += 2) {
                float4 p = *(const float4*)(base + r * ROW_BYTES + d4 * 16);
                float4 q = *(const float4*)(base + RPS * ROW_BYTES + r * ROW_BYTES + d4 * 16);
                float dx = p.x - q.x, dy = p.y - q.y, dz = p.z - q.z, dw = p.w - q.w;
                sdx += dx; sdy += dy; sdz += dz; sdw += dw;
                wl += smooth_l1(dx) + smooth_l1(dy) + smooth_l1(dz) + smooth_l1(dw);
            }
            __syncthreads();   // slot fully consumed by all threads

            if (tid == 0 && s + NSTAGE < nst) {
                const int s2 = s + NSTAGE;
                const int nr2 = min(RPS, rows - s2 * RPS);
                const uint32_t bytes = (uint32_t)nr2 * ROW_BYTES;
                const uint32_t bar = bm + slot * 8;
                const uint32_t base2 = dsm + slot * STAGE_BYTES;
                mbar_expect_tx(bar, 2 * bytes);
                bulk_ld(base2,                   pg + (size_t)s2 * RPS * ROW_BYTES, bytes, bar);
                bulk_ld(base2 + RPS * ROW_BYTES, qg + (size_t)s2 * RPS * ROW_BYTES, bytes, bar);
            }
        }

        // combine the two row-parity halves in shared, then one set of atomics
        __shared__ float s_half[D4 * 4];
        if (th == 1) {
            s_half[d4 * 4 + 0] = sdx; s_half[d4 * 4 + 1] = sdy;
            s_half[d4 * 4 + 2] = sdz; s_half[d4 * 4 + 3] = sdw;
        }
        __syncthreads();
        if (th == 0) {
            const int base = b * DD + d4 * 4;
            atomicAdd(&g_sumdiff[base + 0], sdx + s_half[d4 * 4 + 0]);
            atomicAdd(&g_sumdiff[base + 1], sdy + s_half[d4 * 4 + 1]);
            atomicAdd(&g_sumdiff[base + 2], sdz + s_half[d4 * 4 + 2]);
            atomicAdd(&g_sumdiff[base + 3], sdw + s_half[d4 * 4 + 3]);
        }

        // word-loss partial: block reduce, one atomic per block
        __shared__ float s_wl[256];
        s_wl[tid] = wl;
        __syncthreads();
#pragma unroll
        for (int s = 128; s > 0; s >>= 1) {
            if (tid < s) s_wl[tid] += s_wl[tid + s];
            __syncthreads();
        }
        if (tid == 0) atomicAdd(&g_wl, s_wl[0]);
    }

    // ticket: EVERY block participates (incl. fully-masked early exits)
    __shared__ bool s_last;
    if (tid == 0) {
        __threadfence();                              // release partials
        unsigned old = atomicInc(&g_count, NBLK - 1); // wraps to 0 after NBLK
        s_last = (old == NBLK - 1);
    }
    __syncthreads();
    if (!s_last) return;

    // ---- last block: finalize ----
    __threadfence();                                  // acquire all partials

    __shared__ float s_len[BB];
    __shared__ float s_sumlen;
    if (tid < BB) s_len[tid] = (float)lens[tid];
    __syncthreads();
    if (tid == 0) {
        float s = 0.f;
#pragma unroll
        for (int b2 = 0; b2 < BB; b2++) s += s_len[b2];
        s_sumlen = s;
    }

    float acc = 0.f;
#pragma unroll
    for (int b2 = 0; b2 < BB; b2++) {
        float inv = 1.0f / s_len[b2];
        float m0 = g_sumdiff[b2 * DD + tid]       * inv;
        float m1 = g_sumdiff[b2 * DD + tid + 256] * inv;
        acc += smooth_l1(m0) + smooth_l1(m1);
        g_sumdiff[b2 * DD + tid]       = 0.f;     // re-zero for next invocation
        g_sumdiff[b2 * DD + tid + 256] = 0.f;
    }

    __shared__ float s_red[256];
    s_red[tid] = acc;
    __syncthreads();
#pragma unroll
    for (int s = 128; s > 0; s >>= 1) {
        if (tid < s) s_red[tid] += s_red[tid + s];
        __syncthreads();
    }

    if (tid == 0) {
        float sentence = s_red[0] / (float)DD;                 // sum_b mean_d
        float word     = g_wl / (s_sumlen * (float)DD);
        out[0] = word + sentence / (float)BB;
        g_wl = 0.f;                                            // re-zero
    }
}

extern "C" void kernel_launch(void* const* d_in, const int* in_sizes, int n_in,
                              void* d_out, int out_size)
{
    const float* preds   = (const float*)d_in[0];
    const float* targets = (const float*)d_in[1];
    const int*   lens    = (const int*)d_in[2];
    float*       out     = (float*)d_out;

    cudaFuncSetAttribute(fused_kernel,
                         cudaFuncAttributeMaxDynamicSharedMemorySize, DSMEM_BYTES);
    fused_kernel<<<NBLK, 256, DSMEM_BYTES>>>(preds, targets, lens, out);
}

// round 8
// speedup vs baseline: 1.0156x; 1.0156x over previous
#include <cuda_runtime.h>

#define BB 32
#define TT 2048
#define DD 512
#define D4 128
#define NBLKW 1024           // worker blocks, perfect-balance partition

// Scratch: zero-initialized at module load; finalizing block re-zeros after
// consuming, so every invocation (incl. graph replays) sees zeroed scratch.
__device__ float    g_sumdiff[BB * DD];
__device__ float    g_wl;
__device__ unsigned g_count;   // self-wrapping ticket via atomicInc

__device__ __forceinline__ float smooth_l1(float d) {
    float ad = fabsf(d);
    return (ad < 1.0f) ? 0.5f * d * d : ad - 0.5f;
}

__global__ __launch_bounds__(256) void fused_kernel(
    const float* __restrict__ preds,
    const float* __restrict__ targets,
    const int* __restrict__ lens,
    float* __restrict__ out)
{
    __shared__ int s_lens[BB];
    __shared__ int s_pref[BB + 1];

    const int tid = threadIdx.x;
    if (tid < BB) s_lens[tid] = lens[tid];
    __syncthreads();
    if (tid == 0) {
        int a = 0;
        s_pref[0] = 0;
#pragma unroll
        for (int i = 0; i < BB; i++) { a += s_lens[i]; s_pref[i + 1] = a; }
    }
    __syncthreads();

    const int R    = s_pref[BB];                       // total valid rows
    const int bid  = blockIdx.x;
    const int row0 = (int)((long long)bid       * R / NBLKW);
    const int row1 = (int)((long long)(bid + 1) * R / NBLKW);

    const int d4 = tid & 127;     // float4 lane in D (4 warps cover a 2KB row)
    const int th = tid >> 7;      // two consecutive flattened rows in flight

    const float4* __restrict__ p4 = (const float4*)preds;
    const float4* __restrict__ q4 = (const float4*)targets;

    float sdx = 0.f, sdy = 0.f, sdz = 0.f, sdw = 0.f;
    float wl = 0.f;
    int bcur = -1;

    for (int r = row0 + th; r < row1; r += 2) {
        // locate batch for flattened row r (monotone -> forward scan)
        int bnew = (bcur < 0) ? 0 : bcur;
        while (r >= s_pref[bnew + 1]) bnew++;
        if (bnew != bcur) {
            if (bcur >= 0) {      // flush sentence partials for previous batch
                const int base = bcur * DD + d4 * 4;
                atomicAdd(&g_sumdiff[base + 0], sdx);
                atomicAdd(&g_sumdiff[base + 1], sdy);
                atomicAdd(&g_sumdiff[base + 2], sdz);
                atomicAdd(&g_sumdiff[base + 3], sdw);
                sdx = sdy = sdz = sdw = 0.f;
            }
            bcur = bnew;
        }
        const int t = r - s_pref[bcur];
        const size_t idx = ((size_t)bcur * TT + t) * D4 + d4;
        float4 p = p4[idx];
        float4 q = q4[idx];
        float dx = p.x - q.x, dy = p.y - q.y, dz = p.z - q.z, dw = p.w - q.w;
        sdx += dx; sdy += dy; sdz += dz; sdw += dw;
        wl += smooth_l1(dx) + smooth_l1(dy) + smooth_l1(dz) + smooth_l1(dw);
    }
    if (bcur >= 0) {
        const int base = bcur * DD + d4 * 4;
        atomicAdd(&g_sumdiff[base + 0], sdx);
        atomicAdd(&g_sumdiff[base + 1], sdy);
        atomicAdd(&g_sumdiff[base + 2], sdz);
        atomicAdd(&g_sumdiff[base + 3], sdw);
    }

    // word-loss partial: block reduce, one atomic per block
    __shared__ float s_wl[256];
    s_wl[tid] = wl;
    __syncthreads();
#pragma unroll
    for (int s = 128; s > 0; s >>= 1) {
        if (tid < s) s_wl[tid] += s_wl[tid + s];
        __syncthreads();
    }

    __shared__ bool s_last;
    if (tid == 0) {
        if (s_wl[0] != 0.f) atomicAdd(&g_wl, s_wl[0]);
        __threadfence();                               // release partials
        unsigned old = atomicInc(&g_count, NBLKW - 1); // wraps to 0 after NBLKW
        s_last = (old == NBLKW - 1);
    }
    __syncthreads();
    if (!s_last) return;

    // ---- last block: finalize ----
    __threadfence();                                   // acquire all partials

    __shared__ float s_sumlen;
    if (tid == 0) s_sumlen = (float)R;
    __syncthreads();

    float acc = 0.f;
#pragma unroll
    for (int b2 = 0; b2 < BB; b2++) {
        float inv = 1.0f / (float)s_lens[b2];
        float m0 = g_sumdiff[b2 * DD + tid]       * inv;
        float m1 = g_sumdiff[b2 * DD + tid + 256] * inv;
        acc += smooth_l1(m0) + smooth_l1(m1);
        g_sumdiff[b2 * DD + tid]       = 0.f;      // re-zero for next invocation
        g_sumdiff[b2 * DD + tid + 256] = 0.f;
    }

    __shared__ float s_red[256];
    s_red[tid] = acc;
    __syncthreads();
#pragma unroll
    for (int s = 128; s > 0; s >>= 1) {
        if (tid < s) s_red[tid] += s_red[tid + s];
        __syncthreads();
    }

    if (tid == 0) {
        float sentence = s_red[0] / (float)DD;                 // sum_b mean_d
        float word     = g_wl / (s_sumlen * (float)DD);
        out[0] = word + sentence / (float)BB;
        g_wl = 0.f;                                            // re-zero
    }
}

extern "C" void kernel_launch(void* const* d_in, const int* in_sizes, int n_in,
                              void* d_out, int out_size)
{
    const float* preds   = (const float*)d_in[0];
    const float* targets = (const float*)d_in[1];
    const int*   lens    = (const int*)d_in[2];
    float*       out     = (float*)d_out;

    fused_kernel<<<NBLKW, 256>>>(preds, targets, lens, out);
}